// round 1
// baseline (speedup 1.0000x reference)
#include <cuda_runtime.h>
#include <cuda_bf16.h>
#include <math.h>

// Problem: AdaptiveGraphGenerator. dim=128, B=1, N=1024.
// Key insight: edge_probs = ones_like(probs) -> the entire pairwise edge
// predictor (hi/hj/pair_h/logits/sigmoid, ~270 GFLOP) is dead code.
// adj_matrix = (1.0f > threshold) broadcast over [B,N,N,1].
// Only real compute: node encoder  LN(x@W1+b1) -> GELU -> @W2+b2.
//
// Inputs (metadata order):
//  0 x        [1,1024,128] f32
//  1 W_enc1   [128,256]
//  2 b_enc1   [256]
//  3 ln_g     [256]
//  4 ln_b     [256]
//  5 W_enc2   [256,128]
//  6 b_enc2   [128]
//  7 W_e1     [256,128]   (dead)
//  8 b_e1     [128]       (dead)
//  9 W_e2     [128,1]     (dead)
// 10 b_e2     [1]         (dead)
// 11 threshold[1]
//
// Output: flattened tuple (adj_matrix [1,1024,1024,1], node_feats [1,1024,128])
//         = 1048576 + 131072 = 1179648 f32.

#define DIM 128
#define HID 256
#define NROWS 1024
#define ROWS_PER_BLK 8
#define THREADS 256

__device__ __forceinline__ float gelu_exact(float v) {
    return 0.5f * v * (1.0f + erff(v * 0.70710678118654752f));
}

__global__ __launch_bounds__(THREADS, 4)
void node_encoder_kernel(const float* __restrict__ x,
                         const float* __restrict__ W1,
                         const float* __restrict__ b1,
                         const float* __restrict__ ln_g,
                         const float* __restrict__ ln_b,
                         const float* __restrict__ W2,
                         const float* __restrict__ b2,
                         float* __restrict__ node_out) {
    __shared__ float sx[ROWS_PER_BLK][DIM];       // 4 KB
    __shared__ float sh[ROWS_PER_BLK][HID];       // 8 KB
    __shared__ float s_mean[ROWS_PER_BLK];
    __shared__ float s_rstd[ROWS_PER_BLK];

    const int tid  = threadIdx.x;          // 0..255
    const int row0 = blockIdx.x * ROWS_PER_BLK;

    // Load x tile [8,128] into shared (coalesced: 1024 floats / 256 threads).
    #pragma unroll
    for (int i = tid; i < ROWS_PER_BLK * DIM; i += THREADS) {
        sx[i / DIM][i % DIM] = x[(row0 + i / DIM) * DIM + (i % DIM)];
    }
    __syncthreads();

    // --- GEMM1: h[r][tid] = sum_k x[r][k] * W1[k][tid] + b1[tid] ---
    // Each thread owns hidden column j=tid, 8 row accumulators.
    float acc[ROWS_PER_BLK];
    {
        const float bias = b1[tid];
        #pragma unroll
        for (int r = 0; r < ROWS_PER_BLK; r++) acc[r] = bias;
        #pragma unroll 4
        for (int k = 0; k < DIM; k++) {
            const float w = W1[k * HID + tid];   // coalesced across threads
            const float* xr = &sx[0][k];
            #pragma unroll
            for (int r = 0; r < ROWS_PER_BLK; r++)
                acc[r] = fmaf(xr[r * DIM], w, acc[r]);
        }
    }

    // Stash h into shared for the row-wise LN reduction.
    #pragma unroll
    for (int r = 0; r < ROWS_PER_BLK; r++) sh[r][tid] = acc[r];
    __syncthreads();

    // --- LayerNorm stats: warp w reduces row w (8 warps, 8 rows) ---
    {
        const int wid  = tid >> 5;
        const int lane = tid & 31;
        float s = 0.0f, sq = 0.0f;
        #pragma unroll
        for (int j = lane; j < HID; j += 32) {
            const float v = sh[wid][j];
            s += v; sq += v * v;
        }
        #pragma unroll
        for (int o = 16; o > 0; o >>= 1) {
            s  += __shfl_xor_sync(0xffffffffu, s,  o);
            sq += __shfl_xor_sync(0xffffffffu, sq, o);
        }
        if (lane == 0) {
            const float m   = s * (1.0f / HID);
            const float var = sq * (1.0f / HID) - m * m;
            s_mean[wid] = m;
            s_rstd[wid] = rsqrtf(var + 1e-5f);
        }
    }
    __syncthreads();

    // --- Normalize + affine + GELU (exact erf), write back to shared ---
    {
        const float gg = ln_g[tid];
        const float bb = ln_b[tid];
        #pragma unroll
        for (int r = 0; r < ROWS_PER_BLK; r++) {
            const float v = (acc[r] - s_mean[r]) * s_rstd[r] * gg + bb;
            sh[r][tid] = gelu_exact(v);
        }
    }
    __syncthreads();

    // --- GEMM2: out[r][j] = sum_k gh[r][k] * W2[k][j] + b2[j] ---
    // thread -> col j = tid&127, row group rg = tid>>7 handles rows rg*4..rg*4+3
    {
        const int j  = tid & (DIM - 1);
        const int rg = tid >> 7;
        const float bias = b2[j];
        float o0 = bias, o1 = bias, o2 = bias, o3 = bias;
        const float* g0 = &sh[rg * 4 + 0][0];
        const float* g1 = &sh[rg * 4 + 1][0];
        const float* g2 = &sh[rg * 4 + 2][0];
        const float* g3 = &sh[rg * 4 + 3][0];
        #pragma unroll 4
        for (int k = 0; k < HID; k++) {
            const float w = W2[k * DIM + j];     // coalesced across threads
            o0 = fmaf(g0[k], w, o0);
            o1 = fmaf(g1[k], w, o1);
            o2 = fmaf(g2[k], w, o2);
            o3 = fmaf(g3[k], w, o3);
        }
        const int rbase = row0 + rg * 4;
        node_out[(rbase + 0) * DIM + j] = o0;
        node_out[(rbase + 1) * DIM + j] = o1;
        node_out[(rbase + 2) * DIM + j] = o2;
        node_out[(rbase + 3) * DIM + j] = o3;
    }
}

// adj_matrix = (1.0f > threshold) ? 1 : 0, broadcast over 1024*1024 elements.
__global__ void fill_adj_kernel(float* __restrict__ out,
                                const float* __restrict__ thr,
                                int n_vec4) {
    const float v = (1.0f > thr[0]) ? 1.0f : 0.0f;
    const float4 f4 = make_float4(v, v, v, v);
    const int stride = gridDim.x * blockDim.x;
    for (int i = blockIdx.x * blockDim.x + threadIdx.x; i < n_vec4; i += stride) {
        reinterpret_cast<float4*>(out)[i] = f4;
    }
}

extern "C" void kernel_launch(void* const* d_in, const int* in_sizes, int n_in,
                              void* d_out, int out_size) {
    const float* x    = (const float*)d_in[0];
    const float* W1   = (const float*)d_in[1];
    const float* b1   = (const float*)d_in[2];
    const float* ln_g = (const float*)d_in[3];
    const float* ln_b = (const float*)d_in[4];
    const float* W2   = (const float*)d_in[5];
    const float* b2   = (const float*)d_in[6];
    const float* thr  = (const float*)d_in[11];

    float* out = (float*)d_out;
    float* adj_out  = out;                      // [1,1024,1024,1]
    float* node_out = out + NROWS * NROWS;      // [1,1024,128]

    // adj fill: 1048576 floats = 262144 float4
    const int n_vec4 = (NROWS * NROWS) / 4;
    fill_adj_kernel<<<512, 256>>>(adj_out, thr, n_vec4);

    node_encoder_kernel<<<NROWS / ROWS_PER_BLK, THREADS>>>(
        x, W1, b1, ln_g, ln_b, W2, b2, node_out);
}

// round 2
// speedup vs baseline: 1.0393x; 1.0393x over previous
#include <cuda_runtime.h>
#include <cuda_bf16.h>
#include <math.h>

// AdaptiveGraphGenerator: dim=128, B=1, N=1024.
// edge predictor is dead code (edge_probs = ones). adj = (1.0 > threshold).
// Real work: node encoder LN(x@W1+b1) -> GELU -> @W2+b2.
//
// R2: fused single kernel. 256 blocks x 256 threads, 4 rows/block.
//  - adj slice fill per block (float4 stores)
//  - GEMM1 with 8-wide weight prefetch (MLP=8), x from shared via float4
//  - warp-pair LN reduction
//  - GEMM2 with 8-wide weight prefetch, gelu(h) from shared via float4

#define DIM 128
#define HID 256
#define NROWS 1024
#define ROWS 4
#define THREADS 256
#define NBLOCKS (NROWS / ROWS)   // 256

__device__ __forceinline__ float gelu_exact(float v) {
    return 0.5f * v * (1.0f + erff(v * 0.70710678118654752f));
}

__global__ __launch_bounds__(THREADS, 2)
void fused_kernel(const float* __restrict__ x,
                  const float* __restrict__ W1,
                  const float* __restrict__ b1,
                  const float* __restrict__ ln_g,
                  const float* __restrict__ ln_b,
                  const float* __restrict__ W2,
                  const float* __restrict__ b2,
                  const float* __restrict__ thr,
                  float* __restrict__ adj_out,
                  float* __restrict__ node_out) {
    __shared__ float sx[ROWS][DIM];        // 2 KB
    __shared__ float sh[ROWS][HID];        // 4 KB
    __shared__ float s_part[8][2];         // warp partial sums
    __shared__ float s_mean[ROWS];
    __shared__ float s_rstd[ROWS];

    const int tid  = threadIdx.x;           // 0..255
    const int row0 = blockIdx.x * ROWS;

    // ---- adj fill: this block's 4096-float slice (1024 float4) ----
    {
        const float v = (1.0f > thr[0]) ? 1.0f : 0.0f;
        const float4 f4 = make_float4(v, v, v, v);
        float4* a4 = reinterpret_cast<float4*>(adj_out) + (size_t)blockIdx.x * 1024;
        #pragma unroll
        for (int i = 0; i < 4; i++)
            a4[tid + i * THREADS] = f4;
    }

    // ---- load x tile [4,128] into shared (float4, coalesced) ----
    {
        const float4* x4 = reinterpret_cast<const float4*>(x + (size_t)row0 * DIM);
        float4* sx4 = reinterpret_cast<float4*>(&sx[0][0]);
        if (tid < ROWS * DIM / 4)           // 128 threads carry the tile
            sx4[tid] = x4[tid];
    }
    __syncthreads();

    // ---- GEMM1: h[r][j=tid] = sum_k x[r][k]*W1[k][j] + b1[j] ----
    float acc[ROWS];
    {
        const float bias = __ldg(&b1[tid]);
        #pragma unroll
        for (int r = 0; r < ROWS; r++) acc[r] = bias;

        #pragma unroll 2
        for (int k = 0; k < DIM; k += 8) {
            float w[8];
            #pragma unroll
            for (int u = 0; u < 8; u++)
                w[u] = __ldg(&W1[(k + u) * HID + tid]);   // 8 LDGs batched
            #pragma unroll
            for (int r = 0; r < ROWS; r++) {
                const float4 xa = *reinterpret_cast<const float4*>(&sx[r][k]);
                const float4 xb = *reinterpret_cast<const float4*>(&sx[r][k + 4]);
                acc[r] = fmaf(xa.x, w[0], acc[r]);
                acc[r] = fmaf(xa.y, w[1], acc[r]);
                acc[r] = fmaf(xa.z, w[2], acc[r]);
                acc[r] = fmaf(xa.w, w[3], acc[r]);
                acc[r] = fmaf(xb.x, w[4], acc[r]);
                acc[r] = fmaf(xb.y, w[5], acc[r]);
                acc[r] = fmaf(xb.z, w[6], acc[r]);
                acc[r] = fmaf(xb.w, w[7], acc[r]);
            }
        }
    }

    // ---- LN stats: warp w handles row (w&3), half-columns; register reduce ----
    {
        const int wid  = tid >> 5;
        const int r    = wid & 3;           // row this warp reduces
        // This warp holds columns [wid*32, wid*32+32) of every row in acc,
        // but for reduction each warp reduces ITS OWN acc[r] over its lanes,
        // which covers cols wid*32..wid*32+31 only. Two warps (w, w+4) cover
        // different column blocks of the same row? No — warp w's acc[r] IS
        // columns wid*32+lane. Rows r=wid&3 pairs warps {0,4},{1,5},{2,6},{3,7}
        // covering col blocks {0-31,128-159},... That misses other cols.
        // => must reduce over ALL warps. Do full 2-level reduce instead:
        float s = acc[r];                   // placeholder (overwritten below)
        (void)s;
    }
    // Full reduction: every warp reduces all 4 of its acc values over lanes,
    // writes per-warp partials, then one warp combines 8 partials per row.
    {
        const int wid  = tid >> 5;
        const int lane = tid & 31;
        float ps[ROWS], pq[ROWS];
        #pragma unroll
        for (int r = 0; r < ROWS; r++) { ps[r] = acc[r]; pq[r] = acc[r] * acc[r]; }
        #pragma unroll
        for (int o = 16; o > 0; o >>= 1) {
            #pragma unroll
            for (int r = 0; r < ROWS; r++) {
                ps[r] += __shfl_xor_sync(0xffffffffu, ps[r], o);
                pq[r] += __shfl_xor_sync(0xffffffffu, pq[r], o);
            }
        }
        __shared__ float s_sum[8][ROWS];
        __shared__ float s_sq[8][ROWS];
        if (lane == 0) {
            #pragma unroll
            for (int r = 0; r < ROWS; r++) { s_sum[wid][r] = ps[r]; s_sq[wid][r] = pq[r]; }
        }
        __syncthreads();
        if (tid < ROWS) {                   // thread r finalizes row r
            float s = 0.0f, q = 0.0f;
            #pragma unroll
            for (int w = 0; w < 8; w++) { s += s_sum[w][tid]; q += s_sq[w][tid]; }
            const float m   = s * (1.0f / HID);
            const float var = q * (1.0f / HID) - m * m;
            s_mean[tid] = m;
            s_rstd[tid] = rsqrtf(var + 1e-5f);
        }
        (void)s_part;
    }
    __syncthreads();

    // ---- normalize + affine + GELU -> shared ----
    {
        const float gg = __ldg(&ln_g[tid]);
        const float bb = __ldg(&ln_b[tid]);
        #pragma unroll
        for (int r = 0; r < ROWS; r++) {
            const float v = (acc[r] - s_mean[r]) * s_rstd[r] * gg + bb;
            sh[r][tid] = gelu_exact(v);
        }
    }
    __syncthreads();

    // ---- GEMM2: out[r][j] = sum_k g[r][k]*W2[k][j] + b2[j] ----
    // thread: col j = tid&127, row group rg = tid>>7 -> rows 2rg, 2rg+1
    {
        const int j  = tid & (DIM - 1);
        const int rg = tid >> 7;
        const float bias = __ldg(&b2[j]);
        float o0 = bias, o1 = bias;
        const float* g0 = &sh[rg * 2 + 0][0];
        const float* g1 = &sh[rg * 2 + 1][0];
        #pragma unroll 2
        for (int k = 0; k < HID; k += 8) {
            float w[8];
            #pragma unroll
            for (int u = 0; u < 8; u++)
                w[u] = __ldg(&W2[(k + u) * DIM + j]);
            const float4 a0 = *reinterpret_cast<const float4*>(&g0[k]);
            const float4 a1 = *reinterpret_cast<const float4*>(&g0[k + 4]);
            const float4 c0 = *reinterpret_cast<const float4*>(&g1[k]);
            const float4 c1 = *reinterpret_cast<const float4*>(&g1[k + 4]);
            o0 = fmaf(a0.x, w[0], o0); o1 = fmaf(c0.x, w[0], o1);
            o0 = fmaf(a0.y, w[1], o0); o1 = fmaf(c0.y, w[1], o1);
            o0 = fmaf(a0.z, w[2], o0); o1 = fmaf(c0.z, w[2], o1);
            o0 = fmaf(a0.w, w[3], o0); o1 = fmaf(c0.w, w[3], o1);
            o0 = fmaf(a1.x, w[4], o0); o1 = fmaf(c1.x, w[4], o1);
            o0 = fmaf(a1.y, w[5], o0); o1 = fmaf(c1.y, w[5], o1);
            o0 = fmaf(a1.z, w[6], o0); o1 = fmaf(c1.z, w[6], o1);
            o0 = fmaf(a1.w, w[7], o0); o1 = fmaf(c1.w, w[7], o1);
        }
        const int rbase = row0 + rg * 2;
        node_out[(size_t)(rbase + 0) * DIM + j] = o0;
        node_out[(size_t)(rbase + 1) * DIM + j] = o1;
    }
}

extern "C" void kernel_launch(void* const* d_in, const int* in_sizes, int n_in,
                              void* d_out, int out_size) {
    const float* x    = (const float*)d_in[0];
    const float* W1   = (const float*)d_in[1];
    const float* b1   = (const float*)d_in[2];
    const float* ln_g = (const float*)d_in[3];
    const float* ln_b = (const float*)d_in[4];
    const float* W2   = (const float*)d_in[5];
    const float* b2   = (const float*)d_in[6];
    const float* thr  = (const float*)d_in[11];

    float* out = (float*)d_out;
    float* adj_out  = out;                      // [1,1024,1024,1]
    float* node_out = out + NROWS * NROWS;      // [1,1024,128]

    fused_kernel<<<NBLOCKS, THREADS>>>(x, W1, b1, ln_g, ln_b, W2, b2, thr,
                                       adj_out, node_out);
}

// round 3
// speedup vs baseline: 1.4100x; 1.3567x over previous
#include <cuda_runtime.h>
#include <cuda_bf16.h>
#include <math.h>

// AdaptiveGraphGenerator: dim=128, B=1, N=1024.
// edge predictor is dead code (edge_probs = ones). adj = (1.0 > threshold).
// Real work: node encoder LN(x@W1+b1) -> GELU -> @W2+b2.
//
// R3: 512 blocks x 256 threads, 2 rows/block, launch_bounds(256,4) for ~40% occ.
// 3 barriers (redundant per-thread LN finalize), W2 prefetch overlapped with
// the final barrier. Weights get cross-block L1 reuse (R2 evidence: L2=3.6%).

#define DIM 128
#define HID 256
#define NROWS 1024
#define ROWS 2
#define THREADS 256
#define NBLOCKS (NROWS / ROWS)   // 512

__device__ __forceinline__ float gelu_exact(float v) {
    return 0.5f * v * (1.0f + erff(v * 0.70710678118654752f));
}

__global__ __launch_bounds__(THREADS, 4)
void fused_kernel(const float* __restrict__ x,
                  const float* __restrict__ W1,
                  const float* __restrict__ b1,
                  const float* __restrict__ ln_g,
                  const float* __restrict__ ln_b,
                  const float* __restrict__ W2,
                  const float* __restrict__ b2,
                  const float* __restrict__ thr,
                  float* __restrict__ adj_out,
                  float* __restrict__ node_out) {
    __shared__ float sx[ROWS][DIM];        // 1 KB
    __shared__ float sh[ROWS][HID];        // 2 KB
    __shared__ float s_sum[8][ROWS];
    __shared__ float s_sq[8][ROWS];

    const int tid  = threadIdx.x;           // 0..255
    const int row0 = blockIdx.x * ROWS;

    // ---- adj fill: this block's 2048-float slice (512 float4) ----
    {
        const float v = (1.0f > thr[0]) ? 1.0f : 0.0f;
        const float4 f4 = make_float4(v, v, v, v);
        float4* a4 = reinterpret_cast<float4*>(adj_out) + (size_t)blockIdx.x * 512;
        #pragma unroll
        for (int i = 0; i < 2; i++)
            a4[tid + i * THREADS] = f4;
    }

    // ---- load x tile [2,128] into shared (float4, coalesced) ----
    {
        const float4* x4 = reinterpret_cast<const float4*>(x + (size_t)row0 * DIM);
        float4* sx4 = reinterpret_cast<float4*>(&sx[0][0]);
        if (tid < ROWS * DIM / 4)           // 64 threads carry the tile
            sx4[tid] = x4[tid];
    }
    __syncthreads();

    // ---- GEMM1: h[r][j=tid] = sum_k x[r][k]*W1[k][j] + b1[j] ----
    float acc[ROWS];
    {
        const float bias = __ldg(&b1[tid]);
        #pragma unroll
        for (int r = 0; r < ROWS; r++) acc[r] = bias;

        #pragma unroll 2
        for (int k = 0; k < DIM; k += 8) {
            float w[8];
            #pragma unroll
            for (int u = 0; u < 8; u++)
                w[u] = __ldg(&W1[(k + u) * HID + tid]);   // 8 LDGs batched
            #pragma unroll
            for (int r = 0; r < ROWS; r++) {
                const float4 xa = *reinterpret_cast<const float4*>(&sx[r][k]);
                const float4 xb = *reinterpret_cast<const float4*>(&sx[r][k + 4]);
                acc[r] = fmaf(xa.x, w[0], acc[r]);
                acc[r] = fmaf(xa.y, w[1], acc[r]);
                acc[r] = fmaf(xa.z, w[2], acc[r]);
                acc[r] = fmaf(xa.w, w[3], acc[r]);
                acc[r] = fmaf(xb.x, w[4], acc[r]);
                acc[r] = fmaf(xb.y, w[5], acc[r]);
                acc[r] = fmaf(xb.z, w[6], acc[r]);
                acc[r] = fmaf(xb.w, w[7], acc[r]);
            }
        }
    }

    // ---- LN stats: warp-level shuffle reduce, write per-warp partials ----
    {
        const int wid  = tid >> 5;
        const int lane = tid & 31;
        float ps[ROWS], pq[ROWS];
        #pragma unroll
        for (int r = 0; r < ROWS; r++) { ps[r] = acc[r]; pq[r] = acc[r] * acc[r]; }
        #pragma unroll
        for (int o = 16; o > 0; o >>= 1) {
            #pragma unroll
            for (int r = 0; r < ROWS; r++) {
                ps[r] += __shfl_xor_sync(0xffffffffu, ps[r], o);
                pq[r] += __shfl_xor_sync(0xffffffffu, pq[r], o);
            }
        }
        if (lane == 0) {
            #pragma unroll
            for (int r = 0; r < ROWS; r++) { s_sum[wid][r] = ps[r]; s_sq[wid][r] = pq[r]; }
        }
    }
    __syncthreads();

    // ---- every thread finalizes mean/rstd itself (16 broadcast LDS, no extra
    //      barrier), then normalize + affine + GELU -> shared ----
    {
        float m[ROWS], rstd[ROWS];
        #pragma unroll
        for (int r = 0; r < ROWS; r++) {
            float s = 0.0f, q = 0.0f;
            #pragma unroll
            for (int w = 0; w < 8; w++) { s += s_sum[w][r]; q += s_sq[w][r]; }
            m[r] = s * (1.0f / HID);
            const float var = q * (1.0f / HID) - m[r] * m[r];
            rstd[r] = rsqrtf(var + 1e-5f);
        }
        const float gg = __ldg(&ln_g[tid]);
        const float bb = __ldg(&ln_b[tid]);
        #pragma unroll
        for (int r = 0; r < ROWS; r++) {
            const float v = (acc[r] - m[r]) * rstd[r] * gg + bb;
            sh[r][tid] = gelu_exact(v);
        }
    }

    // ---- GEMM2 setup: prefetch the first W2 group BEFORE the barrier so the
    //      ~234cyc L2 latency hides under the barrier wait ----
    const int j  = tid & (DIM - 1);
    const int rg = tid >> 7;                // row this thread produces
    float w0[8];
    #pragma unroll
    for (int u = 0; u < 8; u++)
        w0[u] = __ldg(&W2[u * DIM + j]);
    const float bias2 = __ldg(&b2[j]);

    __syncthreads();

    // ---- GEMM2: out[rg][j] = sum_k g[rg][k]*W2[k][j] + b2[j] ----
    {
        float o0 = bias2;
        const float* g0 = &sh[rg][0];
        // first group uses prefetched weights
        {
            const float4 a0 = *reinterpret_cast<const float4*>(&g0[0]);
            const float4 a1 = *reinterpret_cast<const float4*>(&g0[4]);
            o0 = fmaf(a0.x, w0[0], o0);
            o0 = fmaf(a0.y, w0[1], o0);
            o0 = fmaf(a0.z, w0[2], o0);
            o0 = fmaf(a0.w, w0[3], o0);
            o0 = fmaf(a1.x, w0[4], o0);
            o0 = fmaf(a1.y, w0[5], o0);
            o0 = fmaf(a1.z, w0[6], o0);
            o0 = fmaf(a1.w, w0[7], o0);
        }
        #pragma unroll 2
        for (int k = 8; k < HID; k += 8) {
            float w[8];
            #pragma unroll
            for (int u = 0; u < 8; u++)
                w[u] = __ldg(&W2[(k + u) * DIM + j]);
            const float4 a0 = *reinterpret_cast<const float4*>(&g0[k]);
            const float4 a1 = *reinterpret_cast<const float4*>(&g0[k + 4]);
            o0 = fmaf(a0.x, w[0], o0);
            o0 = fmaf(a0.y, w[1], o0);
            o0 = fmaf(a0.z, w[2], o0);
            o0 = fmaf(a0.w, w[3], o0);
            o0 = fmaf(a1.x, w[4], o0);
            o0 = fmaf(a1.y, w[5], o0);
            o0 = fmaf(a1.z, w[6], o0);
            o0 = fmaf(a1.w, w[7], o0);
        }
        node_out[(size_t)(row0 + rg) * DIM + j] = o0;
    }
}

extern "C" void kernel_launch(void* const* d_in, const int* in_sizes, int n_in,
                              void* d_out, int out_size) {
    const float* x    = (const float*)d_in[0];
    const float* W1   = (const float*)d_in[1];
    const float* b1   = (const float*)d_in[2];
    const float* ln_g = (const float*)d_in[3];
    const float* ln_b = (const float*)d_in[4];
    const float* W2   = (const float*)d_in[5];
    const float* b2   = (const float*)d_in[6];
    const float* thr  = (const float*)d_in[11];

    float* out = (float*)d_out;
    float* adj_out  = out;                      // [1,1024,1024,1]
    float* node_out = out + NROWS * NROWS;      // [1,1024,128]

    fused_kernel<<<NBLOCKS, THREADS>>>(x, W1, b1, ln_g, ln_b, W2, b2, thr,
                                       adj_out, node_out);
}

// round 4
// speedup vs baseline: 1.6053x; 1.1385x over previous
#include <cuda_runtime.h>
#include <cuda_bf16.h>
#include <math.h>

// AdaptiveGraphGenerator: dim=128, B=1, N=1024.
// edge predictor is dead code (edge_probs = ones). adj = (1.0 > threshold).
// Real work: node encoder LN(x@W1+b1) -> GELU -> @W2+b2.
//
// R4: 512 blocks x 256 threads, 2 rows/block.
//  - GEMM1: split accumulators (4 indep FMA chains), 8-wide weight prefetch
//  - warp-specialized tail: warps 0-3 do GEMM2 (2 rows/thread -> W2 read once
//    per block), warps 4-7 do the adj fill concurrently
//  - W2 group-0 prefetched under the last barrier

#define DIM 128
#define HID 256
#define NROWS 1024
#define ROWS 2
#define THREADS 256
#define NBLOCKS (NROWS / ROWS)   // 512

__device__ __forceinline__ float gelu_exact(float v) {
    return 0.5f * v * (1.0f + erff(v * 0.70710678118654752f));
}

__global__ __launch_bounds__(THREADS, 4)
void fused_kernel(const float* __restrict__ x,
                  const float* __restrict__ W1,
                  const float* __restrict__ b1,
                  const float* __restrict__ ln_g,
                  const float* __restrict__ ln_b,
                  const float* __restrict__ W2,
                  const float* __restrict__ b2,
                  const float* __restrict__ thr,
                  float* __restrict__ adj_out,
                  float* __restrict__ node_out) {
    __shared__ float sx[ROWS][DIM];        // 1 KB
    __shared__ float sh[ROWS][HID];        // 2 KB
    __shared__ float s_sum[8][ROWS];
    __shared__ float s_sq[8][ROWS];

    const int tid  = threadIdx.x;           // 0..255
    const int row0 = blockIdx.x * ROWS;

    // ---- load x tile [2,128] into shared (float4, coalesced) ----
    {
        const float4* x4 = reinterpret_cast<const float4*>(x + (size_t)row0 * DIM);
        float4* sx4 = reinterpret_cast<float4*>(&sx[0][0]);
        if (tid < ROWS * DIM / 4)           // 64 threads carry the tile
            sx4[tid] = x4[tid];
    }
    __syncthreads();

    // ---- GEMM1: h[r][j=tid] = sum_k x[r][k]*W1[k][j] + b1[j] ----
    // Split accumulators: 2 rows x 2 partials = 4 independent FMA chains.
    float acc[ROWS];
    {
        float p0[ROWS], p1[ROWS];
        #pragma unroll
        for (int r = 0; r < ROWS; r++) { p0[r] = 0.0f; p1[r] = 0.0f; }

        #pragma unroll 2
        for (int k = 0; k < DIM; k += 8) {
            float w[8];
            #pragma unroll
            for (int u = 0; u < 8; u++)
                w[u] = __ldg(&W1[(k + u) * HID + tid]);   // 8 LDGs batched
            #pragma unroll
            for (int r = 0; r < ROWS; r++) {
                const float4 xa = *reinterpret_cast<const float4*>(&sx[r][k]);
                const float4 xb = *reinterpret_cast<const float4*>(&sx[r][k + 4]);
                p0[r] = fmaf(xa.x, w[0], p0[r]);
                p1[r] = fmaf(xa.y, w[1], p1[r]);
                p0[r] = fmaf(xa.z, w[2], p0[r]);
                p1[r] = fmaf(xa.w, w[3], p1[r]);
                p0[r] = fmaf(xb.x, w[4], p0[r]);
                p1[r] = fmaf(xb.y, w[5], p1[r]);
                p0[r] = fmaf(xb.z, w[6], p0[r]);
                p1[r] = fmaf(xb.w, w[7], p1[r]);
            }
        }
        const float bias = __ldg(&b1[tid]);
        #pragma unroll
        for (int r = 0; r < ROWS; r++) acc[r] = bias + p0[r] + p1[r];
    }

    // ---- LN stats: warp shuffle reduce -> per-warp partials in shared ----
    {
        const int wid  = tid >> 5;
        const int lane = tid & 31;
        float ps[ROWS], pq[ROWS];
        #pragma unroll
        for (int r = 0; r < ROWS; r++) { ps[r] = acc[r]; pq[r] = acc[r] * acc[r]; }
        #pragma unroll
        for (int o = 16; o > 0; o >>= 1) {
            #pragma unroll
            for (int r = 0; r < ROWS; r++) {
                ps[r] += __shfl_xor_sync(0xffffffffu, ps[r], o);
                pq[r] += __shfl_xor_sync(0xffffffffu, pq[r], o);
            }
        }
        if (lane == 0) {
            #pragma unroll
            for (int r = 0; r < ROWS; r++) { s_sum[wid][r] = ps[r]; s_sq[wid][r] = pq[r]; }
        }
    }
    __syncthreads();

    // ---- per-thread LN finalize (broadcast LDS), normalize+GELU -> shared ----
    {
        float m[ROWS], rstd[ROWS];
        #pragma unroll
        for (int r = 0; r < ROWS; r++) {
            float s = 0.0f, q = 0.0f;
            #pragma unroll
            for (int w = 0; w < 8; w++) { s += s_sum[w][r]; q += s_sq[w][r]; }
            m[r] = s * (1.0f / HID);
            const float var = q * (1.0f / HID) - m[r] * m[r];
            rstd[r] = rsqrtf(var + 1e-5f);
        }
        const float gg = __ldg(&ln_g[tid]);
        const float bb = __ldg(&ln_b[tid]);
        #pragma unroll
        for (int r = 0; r < ROWS; r++) {
            const float v = (acc[r] - m[r]) * rstd[r] * gg + bb;
            sh[r][tid] = gelu_exact(v);
        }
    }

    // ---- prefetch for the specialized tail BEFORE the barrier ----
    const int wid = tid >> 5;
    float w0[8];
    float bias2 = 0.0f;
    float fillv = 0.0f;
    if (wid < 4) {
        // GEMM2 warps: prefetch W2 group 0 + bias (latency hides under barrier)
        #pragma unroll
        for (int u = 0; u < 8; u++)
            w0[u] = __ldg(&W2[u * DIM + tid]);
        bias2 = __ldg(&b2[tid]);
    } else {
        fillv = (1.0f > __ldg(&thr[0])) ? 1.0f : 0.0f;
    }

    __syncthreads();

    if (wid < 4) {
        // ---- GEMM2 (warps 0-3): thread j computes out[0][j] and out[1][j].
        //      W2 read ONCE per block. 4 indep chains (2 rows x 2 partials). ----
        const int j = tid;                    // 0..127
        const float* g0 = &sh[0][0];
        const float* g1 = &sh[1][0];
        float o0a, o0b, o1a, o1b;
        {
            const float4 a0 = *reinterpret_cast<const float4*>(&g0[0]);
            const float4 a1 = *reinterpret_cast<const float4*>(&g0[4]);
            const float4 c0 = *reinterpret_cast<const float4*>(&g1[0]);
            const float4 c1 = *reinterpret_cast<const float4*>(&g1[4]);
            o0a = a0.x * w0[0]; o1a = c0.x * w0[0];
            o0b = a0.y * w0[1]; o1b = c0.y * w0[1];
            o0a = fmaf(a0.z, w0[2], o0a); o1a = fmaf(c0.z, w0[2], o1a);
            o0b = fmaf(a0.w, w0[3], o0b); o1b = fmaf(c0.w, w0[3], o1b);
            o0a = fmaf(a1.x, w0[4], o0a); o1a = fmaf(c1.x, w0[4], o1a);
            o0b = fmaf(a1.y, w0[5], o0b); o1b = fmaf(c1.y, w0[5], o1b);
            o0a = fmaf(a1.z, w0[6], o0a); o1a = fmaf(c1.z, w0[6], o1a);
            o0b = fmaf(a1.w, w0[7], o0b); o1b = fmaf(c1.w, w0[7], o1b);
        }
        #pragma unroll 2
        for (int k = 8; k < HID; k += 8) {
            float w[8];
            #pragma unroll
            for (int u = 0; u < 8; u++)
                w[u] = __ldg(&W2[(k + u) * DIM + j]);
            const float4 a0 = *reinterpret_cast<const float4*>(&g0[k]);
            const float4 a1 = *reinterpret_cast<const float4*>(&g0[k + 4]);
            const float4 c0 = *reinterpret_cast<const float4*>(&g1[k]);
            const float4 c1 = *reinterpret_cast<const float4*>(&g1[k + 4]);
            o0a = fmaf(a0.x, w[0], o0a); o1a = fmaf(c0.x, w[0], o1a);
            o0b = fmaf(a0.y, w[1], o0b); o1b = fmaf(c0.y, w[1], o1b);
            o0a = fmaf(a0.z, w[2], o0a); o1a = fmaf(c0.z, w[2], o1a);
            o0b = fmaf(a0.w, w[3], o0b); o1b = fmaf(c0.w, w[3], o1b);
            o0a = fmaf(a1.x, w[4], o0a); o1a = fmaf(c1.x, w[4], o1a);
            o0b = fmaf(a1.y, w[5], o0b); o1b = fmaf(c1.y, w[5], o1b);
            o0a = fmaf(a1.z, w[6], o0a); o1a = fmaf(c1.z, w[6], o1a);
            o0b = fmaf(a1.w, w[7], o0b); o1b = fmaf(c1.w, w[7], o1b);
        }
        node_out[(size_t)(row0 + 0) * DIM + j] = bias2 + o0a + o0b;
        node_out[(size_t)(row0 + 1) * DIM + j] = bias2 + o1a + o1b;
    } else {
        // ---- adj fill (warps 4-7): this block's 2048-float slice ----
        const int t = tid - 128;              // 0..127
        const float4 f4 = make_float4(fillv, fillv, fillv, fillv);
        float4* a4 = reinterpret_cast<float4*>(adj_out) + (size_t)blockIdx.x * 512;
        #pragma unroll
        for (int i = 0; i < 4; i++)
            a4[t + i * 128] = f4;
    }
}

extern "C" void kernel_launch(void* const* d_in, const int* in_sizes, int n_in,
                              void* d_out, int out_size) {
    const float* x    = (const float*)d_in[0];
    const float* W1   = (const float*)d_in[1];
    const float* b1   = (const float*)d_in[2];
    const float* ln_g = (const float*)d_in[3];
    const float* ln_b = (const float*)d_in[4];
    const float* W2   = (const float*)d_in[5];
    const float* b2   = (const float*)d_in[6];
    const float* thr  = (const float*)d_in[11];

    float* out = (float*)d_out;
    float* adj_out  = out;                      // [1,1024,1024,1]
    float* node_out = out + NROWS * NROWS;      // [1,1024,128]

    fused_kernel<<<NBLOCKS, THREADS>>>(x, W1, b1, ln_g, ln_b, W2, b2, thr,
                                       adj_out, node_out);
}

// round 5
// speedup vs baseline: 2.0239x; 1.2608x over previous
#include <cuda_runtime.h>
#include <cuda_bf16.h>
#include <math.h>

// AdaptiveGraphGenerator: dim=128, B=1, N=1024.
// edge predictor is dead code (edge_probs = ones). adj = (1.0 > threshold).
// Real work: node encoder LN(x@W1+b1) -> GELU -> @W2+b2.
//
// R5: LSU-instruction-bound fix. Each GEMM reads its weight matrix exactly
// once per block via LDG.128 (thread owns 4 cols x both rows x a k-slice),
// cutting warp-LDG count ~4x (2000 -> ~512 per block). k-partials combined
// through conflict-free shared scratch. 512 blocks x 256 threads.

#define DIM 128
#define HID 256
#define NROWS 1024
#define ROWS 2
#define THREADS 256
#define NBLOCKS (NROWS / ROWS)   // 512

__device__ __forceinline__ float gelu_exact(float v) {
    return 0.5f * v * (1.0f + erff(v * 0.70710678118654752f));
}

__global__ __launch_bounds__(THREADS, 4)
void fused_kernel(const float* __restrict__ x,
                  const float* __restrict__ W1,
                  const float* __restrict__ b1,
                  const float* __restrict__ ln_g,
                  const float* __restrict__ ln_b,
                  const float* __restrict__ W2,
                  const float* __restrict__ b2,
                  const float* __restrict__ thr,
                  float* __restrict__ adj_out,
                  float* __restrict__ node_out) {
    __shared__ float sx[ROWS][DIM];        // 1 KB
    __shared__ float scratch[2048];        // 8 KB: p1[4][2][256] then p2[8][2][128]
    __shared__ float sh[ROWS][HID];        // 2 KB gelu(h)
    __shared__ float s_sum[8][ROWS];
    __shared__ float s_sq[8][ROWS];

    const int tid  = threadIdx.x;           // 0..255
    const int row0 = blockIdx.x * ROWS;

    // ---- early scalar prefetches (latency hidden under GEMM1) ----
    const float tv    = __ldg(&thr[0]);
    const float bias1 = __ldg(&b1[tid]);
    const float gg    = __ldg(&ln_g[tid]);
    const float bb    = __ldg(&ln_b[tid]);
    const float bias2 = __ldg(&b2[tid & (DIM - 1)]);

    // ---- load x tile [2,128] into shared (float4, coalesced) ----
    {
        const float4* x4 = reinterpret_cast<const float4*>(x + (size_t)row0 * DIM);
        float4* sx4 = reinterpret_cast<float4*>(&sx[0][0]);
        if (tid < ROWS * DIM / 4)           // 64 threads carry the tile
            sx4[tid] = x4[tid];
    }

    // ---- adj fill: this block's 2048-float slice (512 float4) ----
    {
        const float v = (1.0f > tv) ? 1.0f : 0.0f;
        const float4 f4 = make_float4(v, v, v, v);
        float4* a4 = reinterpret_cast<float4*>(adj_out) + (size_t)blockIdx.x * 512;
        a4[tid]       = f4;
        a4[tid + 256] = f4;
    }
    __syncthreads();

    // ---- GEMM1: thread = (cg = tid&63 -> cols 4cg..4cg+3, h = tid>>6 -> k in
    //      [32h,32h+32)). W1 read exactly once per block, LDG.128. ----
    {
        const int cg = tid & 63;
        const int h  = tid >> 6;            // 0..3
        const float* w1p = W1 + (size_t)(h * 32) * HID + 4 * cg;
        float a00 = 0.f, a01 = 0.f, a02 = 0.f, a03 = 0.f;
        float a10 = 0.f, a11 = 0.f, a12 = 0.f, a13 = 0.f;
        #pragma unroll 8
        for (int kk = 0; kk < 32; kk++) {
            const float4 w4 = *reinterpret_cast<const float4*>(w1p + kk * HID);
            const int k = h * 32 + kk;
            const float x0 = sx[0][k];
            const float x1 = sx[1][k];
            a00 = fmaf(x0, w4.x, a00);  a10 = fmaf(x1, w4.x, a10);
            a01 = fmaf(x0, w4.y, a01);  a11 = fmaf(x1, w4.y, a11);
            a02 = fmaf(x0, w4.z, a02);  a12 = fmaf(x1, w4.z, a12);
            a03 = fmaf(x0, w4.w, a03);  a13 = fmaf(x1, w4.w, a13);
        }
        // p1[h][r][c] = scratch[(h*2+r)*256 + c]; STS.128 conflict-free
        *reinterpret_cast<float4*>(&scratch[(h * 2 + 0) * 256 + 4 * cg]) =
            make_float4(a00, a01, a02, a03);
        *reinterpret_cast<float4*>(&scratch[(h * 2 + 1) * 256 + 4 * cg]) =
            make_float4(a10, a11, a12, a13);
    }
    __syncthreads();

    // ---- combine k-partials + LN stats (thread t owns col c = t, both rows) ----
    float v0, v1;
    {
        const int c = tid;
        v0 = scratch[0 * 512 + c]       + scratch[1 * 512 + c]
           + scratch[2 * 512 + c]       + scratch[3 * 512 + c] + bias1;
        v1 = scratch[0 * 512 + 256 + c] + scratch[1 * 512 + 256 + c]
           + scratch[2 * 512 + 256 + c] + scratch[3 * 512 + 256 + c] + bias1;

        const int wid  = tid >> 5;
        const int lane = tid & 31;
        float s0 = v0, q0 = v0 * v0, s1 = v1, q1 = v1 * v1;
        #pragma unroll
        for (int o = 16; o > 0; o >>= 1) {
            s0 += __shfl_xor_sync(0xffffffffu, s0, o);
            q0 += __shfl_xor_sync(0xffffffffu, q0, o);
            s1 += __shfl_xor_sync(0xffffffffu, s1, o);
            q1 += __shfl_xor_sync(0xffffffffu, q1, o);
        }
        if (lane == 0) {
            s_sum[wid][0] = s0; s_sq[wid][0] = q0;
            s_sum[wid][1] = s1; s_sq[wid][1] = q1;
        }
    }
    __syncthreads();

    // ---- per-thread LN finalize + GELU -> sh ----
    {
        float s0 = 0.f, q0 = 0.f, s1 = 0.f, q1 = 0.f;
        #pragma unroll
        for (int w = 0; w < 8; w++) {
            s0 += s_sum[w][0]; q0 += s_sq[w][0];
            s1 += s_sum[w][1]; q1 += s_sq[w][1];
        }
        const float m0 = s0 * (1.0f / HID);
        const float m1 = s1 * (1.0f / HID);
        const float r0 = rsqrtf(q0 * (1.0f / HID) - m0 * m0 + 1e-5f);
        const float r1 = rsqrtf(q1 * (1.0f / HID) - m1 * m1 + 1e-5f);
        sh[0][tid] = gelu_exact((v0 - m0) * r0 * gg + bb);
        sh[1][tid] = gelu_exact((v1 - m1) * r1 * gg + bb);
    }
    __syncthreads();

    // ---- GEMM2: thread = (cg2 = tid&31 -> cols 4cg2.., h2 = tid>>5 -> k in
    //      [32h2,32h2+32)). W2 read exactly once per block, LDG.128. ----
    {
        const int cg2 = tid & 31;
        const int h2  = tid >> 5;           // 0..7
        const float* w2p = W2 + (size_t)(h2 * 32) * DIM + 4 * cg2;
        float a00 = 0.f, a01 = 0.f, a02 = 0.f, a03 = 0.f;
        float a10 = 0.f, a11 = 0.f, a12 = 0.f, a13 = 0.f;
        #pragma unroll 8
        for (int kk = 0; kk < 32; kk++) {
            const float4 w4 = *reinterpret_cast<const float4*>(w2p + kk * DIM);
            const int k = h2 * 32 + kk;
            const float g0 = sh[0][k];
            const float g1 = sh[1][k];
            a00 = fmaf(g0, w4.x, a00);  a10 = fmaf(g1, w4.x, a10);
            a01 = fmaf(g0, w4.y, a01);  a11 = fmaf(g1, w4.y, a11);
            a02 = fmaf(g0, w4.z, a02);  a12 = fmaf(g1, w4.z, a12);
            a03 = fmaf(g0, w4.w, a03);  a13 = fmaf(g1, w4.w, a13);
        }
        // p2[h][r][c] = scratch[(h*2+r)*128 + c]; STS.128 conflict-free
        *reinterpret_cast<float4*>(&scratch[(h2 * 2 + 0) * 128 + 4 * cg2]) =
            make_float4(a00, a01, a02, a03);
        *reinterpret_cast<float4*>(&scratch[(h2 * 2 + 1) * 128 + 4 * cg2]) =
            make_float4(a10, a11, a12, a13);
    }
    __syncthreads();

    // ---- combine GEMM2 k-partials + store (thread t -> row tid>>7, col tid&127) ----
    {
        const int r = tid >> 7;
        const int c = tid & (DIM - 1);
        float o = bias2;
        #pragma unroll
        for (int hh = 0; hh < 8; hh++)
            o += scratch[(hh * 2 + r) * 128 + c];
        node_out[(size_t)(row0 + r) * DIM + c] = o;
    }
}

extern "C" void kernel_launch(void* const* d_in, const int* in_sizes, int n_in,
                              void* d_out, int out_size) {
    const float* x    = (const float*)d_in[0];
    const float* W1   = (const float*)d_in[1];
    const float* b1   = (const float*)d_in[2];
    const float* ln_g = (const float*)d_in[3];
    const float* ln_b = (const float*)d_in[4];
    const float* W2   = (const float*)d_in[5];
    const float* b2   = (const float*)d_in[6];
    const float* thr  = (const float*)d_in[11];

    float* out = (float*)d_out;
    float* adj_out  = out;                      // [1,1024,1024,1]
    float* node_out = out + NROWS * NROWS;      // [1,1024,128]

    fused_kernel<<<NBLOCKS, THREADS>>>(x, W1, b1, ln_g, ln_b, W2, b2, thr,
                                       adj_out, node_out);
}